// round 15
// baseline (speedup 1.0000x reference)
#include <cuda_runtime.h>
#include <cuda_fp16.h>
#include <cstdint>
#include <cstddef>

// ---------------------------------------------------------------------------
// GCN: 3x GCNConv(128->128) + lin(128->128,relu) + lin(128->40) + log_softmax
// BM=128 fp16 MMA GEMMs + 16-lane/node uint4 gather agg (8-edge unroll).
// Single-pass bucket CSR + 4-chunk cross-stream agg/GEMM pipelining with
// 3-buffer rotation (agg S->T, gemm T->U, U != S: no WAR on the gather src).
// ---------------------------------------------------------------------------

#define NMAX 100000
#define F    128
#define NCLS 40
#define CAP  128          // neighbor bucket capacity (deg ~ Poisson(16))
#define BM   128
#define NCH  4            // pipeline chunks

__device__ __half g_Ha[(size_t)NMAX * F];
__device__ __half g_Hb[(size_t)NMAX * F];
__device__ __half g_Hc[(size_t)NMAX * F];
__device__ float  g_dinv[NMAX];
__device__ int    g_cnt[NMAX];
__device__ int    g_bkt[(size_t)NMAX * CAP];  // bucket adjacency (51.2 MB)
__device__ __half g_Wh[5 * F * F];            // weights [n][k] fp16
__device__ float  g_b2p[F];
__device__ int    g_is64;

__device__ __forceinline__ float4 h4tof4(uint2 u) {
    __half2 a = *(__half2*)&u.x, b = *(__half2*)&u.y;
    float2 fa = __half22float2(a), fb = __half22float2(b);
    return make_float4(fa.x, fa.y, fb.x, fb.y);
}

// ---------------------------------------------------------------------------
__global__ void setupA_kernel(const unsigned int* __restrict__ w, int M) {
    if (blockIdx.x == 0) {
        __shared__ int found;
        if (threadIdx.x == 0) found = 0;
        __syncthreads();
        for (int i = threadIdx.x; i < 2048; i += blockDim.x)
            if (w[2 * i + 1] != 0u) atomicOr(&found, 1);
        __syncthreads();
        if (threadIdx.x == 0) g_is64 = found ? 0 : 1;
    }
    int stride = gridDim.x * blockDim.x;
    for (int i = blockIdx.x * blockDim.x + threadIdx.x; i < M; i += stride)
        g_cnt[i] = 0;
}

__global__ void setupW_kernel(const float* __restrict__ W1,
                              const float* __restrict__ W2,
                              const float* __restrict__ W3,
                              const float* __restrict__ L1,
                              const float* __restrict__ L2,
                              const float* __restrict__ b2) {
    int stride = gridDim.x * blockDim.x;
    int tid0 = blockIdx.x * blockDim.x + threadIdx.x;
    for (int idx = tid0; idx < 5 * F * F; idx += stride) {
        int wi = idx >> 14;
        int r = idx & 16383;
        int n = r >> 7, k = r & 127;
        float v;
        switch (wi) {
            case 0: v = W1[k * F + n]; break;
            case 1: v = W2[k * F + n]; break;
            case 2: v = W3[k * F + n]; break;
            case 3: v = L1[k * F + n]; break;
            default: v = (n < NCLS) ? L2[k * NCLS + n] : 0.0f; break;
        }
        g_Wh[idx] = __float2half_rn(v);
    }
    for (int i = tid0; i < F; i += stride)
        g_b2p[i] = (i < NCLS) ? b2[i] : 0.0f;
}

__device__ __forceinline__ void load_edge(const void* ei, long long e, long long E,
                                          int& s, int& d) {
    if (g_is64) {
        const long long* p = (const long long*)ei;
        s = (int)p[e];
        d = (int)p[E + e];
    } else {
        const int* p = (const int*)ei;
        s = p[e];
        d = p[E + e];
    }
}

// Single-pass bucket CSR build.
__global__ void bucket_fill_kernel(const void* __restrict__ ei, int E) {
    int e = blockIdx.x * blockDim.x + threadIdx.x;
    if (e >= E) return;
    int s, d;
    load_edge(ei, e, E, s, d);
    int p = atomicAdd(&g_cnt[d], 1);
    if (p < CAP) g_bkt[(size_t)d * CAP + p] = s;
}

__global__ void dinv_kernel(int M) {
    int i = blockIdx.x * blockDim.x + threadIdx.x;
    if (i < M) g_dinv[i] = rsqrtf((float)g_cnt[i] + 1.0f);
}

// ---------------------------------------------------------------------------
// GEMM tile kernel. 256 threads, 128 rows x full K=128. tile0 = tile offset.
//  IN:  0 = fp32 global (x), 1 = half global
//  OUT: 0 = Hdst = h*dinv[row], 1 = Hdst = relu(h+obias), 2 = lsm -> out,
//       3 = Hdst = h (raw)
// ---------------------------------------------------------------------------
__device__ __forceinline__ void mma_f16(float* d, const uint32_t* a, const uint32_t* b) {
    asm volatile(
        "mma.sync.aligned.m16n8k16.row.col.f32.f16.f16.f32 "
        "{%0,%1,%2,%3}, {%4,%5,%6,%7}, {%8,%9}, {%0,%1,%2,%3};"
        : "+f"(d[0]), "+f"(d[1]), "+f"(d[2]), "+f"(d[3])
        : "r"(a[0]), "r"(a[1]), "r"(a[2]), "r"(a[3]), "r"(b[0]), "r"(b[1]));
}

__device__ __forceinline__ void ldmx4(uint32_t* r, uint32_t addr) {
    asm volatile("ldmatrix.sync.aligned.m8n8.x4.shared.b16 {%0,%1,%2,%3}, [%4];"
                 : "=r"(r[0]), "=r"(r[1]), "=r"(r[2]), "=r"(r[3]) : "r"(addr));
}

__device__ __forceinline__ void cp16(uint32_t dst, const void* src, int sz) {
    asm volatile("cp.async.cg.shared.global [%0], [%1], 16, %2;"
                 :: "r"(dst), "l"(src), "r"(sz));
}

__device__ __forceinline__ uint32_t swz(int r, int c) {
    return (uint32_t)(r * 256 + ((c ^ (r & 7)) << 4));
}

template <int IN, int OUT>
__global__ void __launch_bounds__(256, 2) gemm_kernel(
    const float* __restrict__ Ax, const __half* __restrict__ Hsrc,
    __half* __restrict__ Hdst, const __half* __restrict__ Wt,
    const float* __restrict__ obias, float* __restrict__ out,
    int tile0, int M)
{
    extern __shared__ __align__(16) char sm[];
    uint32_t sbase;
    asm("{ .reg .u64 t; cvta.to.shared.u64 t, %1; cvt.u32.u64 %0, t; }"
        : "=r"(sbase) : "l"(sm));
    const uint32_t sA = sbase;
    const uint32_t sB = sbase + 32768;

    const int tid = threadIdx.x;
    const int lane = tid & 31;
    const int wid = tid >> 5;
    const int wm = wid & 1;
    const int wn = wid >> 1;
    const int tg = lane >> 2;
    const int tm = lane & 3;
    const int row0 = (tile0 + blockIdx.x) * BM;

    // B prefetch
#pragma unroll
    for (int p = 0; p < 8; p++) {
        int q = p * 256 + tid;
        int r = q >> 4, c = q & 15;
        cp16(sB + swz(r, c), Wt + (size_t)r * F + c * 8, 16);
    }

    // A tile
    if (IN == 1) {
#pragma unroll
        for (int p = 0; p < 8; p++) {
            int q = p * 256 + tid;
            int r = q >> 4, c = q & 15;
            int gr = row0 + r;
            cp16(sA + swz(r, c), Hsrc + (size_t)((gr < M) ? gr : 0) * F + c * 8,
                 (gr < M) ? 16 : 0);
        }
        asm volatile("cp.async.commit_group;" ::: "memory");
    } else {
        asm volatile("cp.async.commit_group;" ::: "memory");
#pragma unroll
        for (int p = 0; p < 8; p++) {
            int q = p * 256 + tid;
            int r = q >> 4, c = q & 15;
            int gr = row0 + r;
            float4 v0, v1;
            if (gr < M) {
                size_t o = (size_t)gr * F + c * 8;
                v0 = *(const float4*)(Ax + o);
                v1 = *(const float4*)(Ax + o + 4);
            } else {
                v0 = v1 = make_float4(0.f, 0.f, 0.f, 0.f);
            }
            __half2 a = __floats2half2_rn(v0.x, v0.y);
            __half2 b = __floats2half2_rn(v0.z, v0.w);
            __half2 cc = __floats2half2_rn(v1.x, v1.y);
            __half2 d = __floats2half2_rn(v1.z, v1.w);
            uint32_t ad = sA + swz(r, c);
            asm volatile("st.shared.v4.b32 [%0], {%1,%2,%3,%4};"
                         :: "r"(ad), "r"(*(uint32_t*)&a), "r"(*(uint32_t*)&b),
                            "r"(*(uint32_t*)&cc), "r"(*(uint32_t*)&d));
        }
    }

    asm volatile("cp.async.wait_group 0;" ::: "memory");
    __syncthreads();

    float acc[4][4][4];
#pragma unroll
    for (int mt = 0; mt < 4; mt++)
#pragma unroll
        for (int nt = 0; nt < 4; nt++)
#pragma unroll
            for (int j = 0; j < 4; j++) acc[mt][nt][j] = 0.0f;

#pragma unroll
    for (int kb = 0; kb < 8; kb++) {
        uint32_t af[4][4], bf[2][4];
#pragma unroll
        for (int mt = 0; mt < 4; mt++) {
            int row = wm * 64 + mt * 16 + (lane & 15);
            int cc = kb * 2 + (lane >> 4);
            ldmx4(af[mt], sA + swz(row, cc));
        }
#pragma unroll
        for (int q = 0; q < 2; q++) {
            int n = wn * 32 + q * 16 + ((lane >> 4) << 3) + (lane & 7);
            int cc = kb * 2 + ((lane >> 3) & 1);
            ldmx4(bf[q], sB + swz(n, cc));
        }
#pragma unroll
        for (int mt = 0; mt < 4; mt++)
#pragma unroll
            for (int nt = 0; nt < 4; nt++)
                mma_f16(acc[mt][nt], af[mt], &bf[nt >> 1][2 * (nt & 1)]);
    }
    __syncthreads();

    // Epilogue
    if (OUT == 2) {
        float* stg = (float*)(sm + 32768);  // [128][44]
#pragma unroll
        for (int mt = 0; mt < 4; mt++) {
            int rl0 = wm * 64 + mt * 16 + tg;
#pragma unroll
            for (int nt = 0; nt < 4; nt++) {
                int c = wn * 32 + nt * 8 + 2 * tm;
                if (c < NCLS) {
                    float b0 = obias[c], b1 = obias[c + 1];
                    stg[rl0 * 44 + c] = acc[mt][nt][0] + b0;
                    stg[rl0 * 44 + c + 1] = acc[mt][nt][1] + b1;
                    stg[(rl0 + 8) * 44 + c] = acc[mt][nt][2] + b0;
                    stg[(rl0 + 8) * 44 + c + 1] = acc[mt][nt][3] + b1;
                }
            }
        }
        __syncthreads();
        if (tid < 128) {
            int gr = row0 + tid;
            if (gr < M) {
                const float* rowp = stg + tid * 44;
                float m = -1e30f;
#pragma unroll
                for (int c = 0; c < NCLS; c++) m = fmaxf(m, rowp[c]);
                float s = 0.f;
#pragma unroll
                for (int c = 0; c < NCLS; c++) s += expf(rowp[c] - m);
                float lse = m + logf(s);
                float* op = out + (size_t)gr * NCLS;
#pragma unroll
                for (int c = 0; c < NCLS; c += 4) {
                    float4 v = make_float4(rowp[c] - lse, rowp[c + 1] - lse,
                                           rowp[c + 2] - lse, rowp[c + 3] - lse);
                    *(float4*)(op + c) = v;
                }
            }
        }
    } else {
#pragma unroll
        for (int mt = 0; mt < 4; mt++) {
            int rl0 = wm * 64 + mt * 16 + tg;
            float dv0 = 1.f, dv1 = 1.f;
            if (OUT == 0) {
                int r0g = row0 + rl0, r1g = r0g + 8;
                dv0 = (r0g < M) ? g_dinv[r0g] : 0.f;
                dv1 = (r1g < M) ? g_dinv[r1g] : 0.f;
            }
#pragma unroll
            for (int nt = 0; nt < 4; nt++) {
                int c = wn * 32 + nt * 8 + 2 * tm;
                __half2 v0, v1;
                if (OUT == 0 || OUT == 3) {
                    v0 = __floats2half2_rn(acc[mt][nt][0] * dv0, acc[mt][nt][1] * dv0);
                    v1 = __floats2half2_rn(acc[mt][nt][2] * dv1, acc[mt][nt][3] * dv1);
                } else {
                    float b0 = obias[c], b1 = obias[c + 1];
                    v0 = __floats2half2_rn(fmaxf(acc[mt][nt][0] + b0, 0.f),
                                           fmaxf(acc[mt][nt][1] + b1, 0.f));
                    v1 = __floats2half2_rn(fmaxf(acc[mt][nt][2] + b0, 0.f),
                                           fmaxf(acc[mt][nt][3] + b1, 0.f));
                }
                uint32_t a0 = sA + swz(rl0, c >> 3) + (c & 7) * 2;
                uint32_t a1 = sA + swz(rl0 + 8, c >> 3) + (c & 7) * 2;
                asm volatile("st.shared.b32 [%0], %1;" :: "r"(a0), "r"(*(uint32_t*)&v0));
                asm volatile("st.shared.b32 [%0], %1;" :: "r"(a1), "r"(*(uint32_t*)&v1));
            }
        }
        __syncthreads();
#pragma unroll
        for (int p = 0; p < 8; p++) {
            int q = p * 256 + tid;
            int r = q >> 4, c = q & 15;
            int gr = row0 + r;
            if (gr < M) {
                uint32_t a = sA + swz(r, c);
                uint4 v;
                asm volatile("ld.shared.v4.b32 {%0,%1,%2,%3}, [%4];"
                             : "=r"(v.x), "=r"(v.y), "=r"(v.z), "=r"(v.w) : "r"(a));
                *(uint4*)(Hdst + (size_t)gr * F + c * 8) = v;
            }
        }
    }
}

// ---------------------------------------------------------------------------
// Bucket aggregation, 16 lanes/node, uint4 loads, 8-edge unroll.
// Node range [n0, n1). dst[n] = relu(dinv[n]*(sum + self) + bias).
// ---------------------------------------------------------------------------
template <bool RAW>
__global__ void agg_kernel(const __half* __restrict__ Hsrc,
                           __half* __restrict__ dst,
                           const float* __restrict__ bias, int n0, int n1) {
    long long t = (long long)blockIdx.x * blockDim.x + threadIdx.x;
    long long n = n0 + (t >> 4);
    if (n >= n1) return;
    int lane = (int)(t & 15);
    const uint4* H = (const uint4*)Hsrc;
    float dn = g_dinv[n];

    uint4 u = H[n * 16 + lane];
    float4 aclo = h4tof4(make_uint2(u.x, u.y));
    float4 achi = h4tof4(make_uint2(u.z, u.w));
    if (RAW) {
        aclo.x *= dn; aclo.y *= dn; aclo.z *= dn; aclo.w *= dn;
        achi.x *= dn; achi.y *= dn; achi.z *= dn; achi.w *= dn;
    }

    int deg = g_cnt[n];
    if (deg > CAP) deg = CAP;
    const int* nb = g_bkt + (size_t)n * CAP;
    int e = 0;

    for (; e + 7 < deg; e += 8) {
        int s[8];
#pragma unroll
        for (int j = 0; j < 8; j++) s[j] = __ldg(&nb[e + j]);
        float d[8];
#pragma unroll
        for (int j = 0; j < 8; j++) d[j] = RAW ? __ldg(&g_dinv[s[j]]) : 1.f;
        uint4 uu[8];
#pragma unroll
        for (int j = 0; j < 8; j++) uu[j] = H[(size_t)s[j] * 16 + lane];
#pragma unroll
        for (int j = 0; j < 8; j++) {
            float4 a = h4tof4(make_uint2(uu[j].x, uu[j].y));
            float4 b = h4tof4(make_uint2(uu[j].z, uu[j].w));
            if (RAW) {
                aclo.x = fmaf(a.x, d[j], aclo.x);
                aclo.y = fmaf(a.y, d[j], aclo.y);
                aclo.z = fmaf(a.z, d[j], aclo.z);
                aclo.w = fmaf(a.w, d[j], aclo.w);
                achi.x = fmaf(b.x, d[j], achi.x);
                achi.y = fmaf(b.y, d[j], achi.y);
                achi.z = fmaf(b.z, d[j], achi.z);
                achi.w = fmaf(b.w, d[j], achi.w);
            } else {
                aclo.x += a.x; aclo.y += a.y; aclo.z += a.z; aclo.w += a.w;
                achi.x += b.x; achi.y += b.y; achi.z += b.z; achi.w += b.w;
            }
        }
    }
    for (; e < deg; e++) {
        int s0 = __ldg(&nb[e]);
        float d0 = RAW ? __ldg(&g_dinv[s0]) : 1.f;
        uint4 u0 = H[(size_t)s0 * 16 + lane];
        float4 a0 = h4tof4(make_uint2(u0.x, u0.y)), b0 = h4tof4(make_uint2(u0.z, u0.w));
        aclo.x += a0.x * d0; aclo.y += a0.y * d0;
        aclo.z += a0.z * d0; aclo.w += a0.w * d0;
        achi.x += b0.x * d0; achi.y += b0.y * d0;
        achi.z += b0.z * d0; achi.w += b0.w * d0;
    }
    float4 blo = *(const float4*)(bias + lane * 8);
    float4 bhi = *(const float4*)(bias + lane * 8 + 4);
    __half2 o0 = __floats2half2_rn(fmaxf(fmaf(aclo.x, dn, blo.x), 0.f),
                                   fmaxf(fmaf(aclo.y, dn, blo.y), 0.f));
    __half2 o1 = __floats2half2_rn(fmaxf(fmaf(aclo.z, dn, blo.z), 0.f),
                                   fmaxf(fmaf(aclo.w, dn, blo.w), 0.f));
    __half2 o2 = __floats2half2_rn(fmaxf(fmaf(achi.x, dn, bhi.x), 0.f),
                                   fmaxf(fmaf(achi.y, dn, bhi.y), 0.f));
    __half2 o3 = __floats2half2_rn(fmaxf(fmaf(achi.z, dn, bhi.z), 0.f),
                                   fmaxf(fmaf(achi.w, dn, bhi.w), 0.f));
    uint4 outv;
    outv.x = *(uint32_t*)&o0; outv.y = *(uint32_t*)&o1;
    outv.z = *(uint32_t*)&o2; outv.w = *(uint32_t*)&o3;
    ((uint4*)dst)[n * 16 + lane] = outv;
}

// ---------------------------------------------------------------------------
extern "C" void kernel_launch(void* const* d_in, const int* in_sizes, int n_in,
                              void* d_out, int out_size) {
    const float* x      = (const float*)d_in[0];
    const void*  ei     = d_in[1];
    const float* W1     = (const float*)d_in[2];
    const float* b1     = (const float*)d_in[3];
    const float* W2     = (const float*)d_in[4];
    const float* b2     = (const float*)d_in[5];
    const float* W3     = (const float*)d_in[6];
    const float* b3     = (const float*)d_in[7];
    const float* lin1_w = (const float*)d_in[8];
    const float* lin1_b = (const float*)d_in[9];
    const float* lin2_w = (const float*)d_in[10];
    const float* lin2_b = (const float*)d_in[11];
    float* out = (float*)d_out;

    int M = in_sizes[0] / F;
    int E = in_sizes[1] / 2;
    const int SMEM = 65536;

    static cudaStream_t s2 = nullptr;
    static cudaEvent_t ev[24];
    static bool init_done = false;
    if (!init_done) {
        cudaFuncSetAttribute(gemm_kernel<0, 3>, cudaFuncAttributeMaxDynamicSharedMemorySize, SMEM);
        cudaFuncSetAttribute(gemm_kernel<1, 0>, cudaFuncAttributeMaxDynamicSharedMemorySize, SMEM);
        cudaFuncSetAttribute(gemm_kernel<1, 1>, cudaFuncAttributeMaxDynamicSharedMemorySize, SMEM);
        cudaFuncSetAttribute(gemm_kernel<1, 2>, cudaFuncAttributeMaxDynamicSharedMemorySize, SMEM);
        cudaStreamCreateWithFlags(&s2, cudaStreamNonBlocking);
        for (int i = 0; i < 24; i++)
            cudaEventCreateWithFlags(&ev[i], cudaEventDisableTiming);
        init_done = true;
    }

    __half *Ha, *Hb, *Hc, *Wbase;
    float* b2p;
    cudaGetSymbolAddress((void**)&Wbase, g_Wh);
    cudaGetSymbolAddress((void**)&Ha, g_Ha);
    cudaGetSymbolAddress((void**)&Hb, g_Hb);
    cudaGetSymbolAddress((void**)&Hc, g_Hc);
    cudaGetSymbolAddress((void**)&b2p, g_b2p);

    int nt = (M + BM - 1) / BM;
    int tpc = (nt + NCH - 1) / NCH;       // tiles per chunk
    int npc = tpc * BM;                   // nodes per chunk
    int evi = 0;

    // ---- Front: fork bucket CSR chain to s2 after setupA ----
    setupA_kernel<<<160, 256>>>((const unsigned int*)ei, M);
    cudaEventRecord(ev[evi], 0);
    cudaStreamWaitEvent(s2, ev[evi], 0);
    evi++;
    bucket_fill_kernel<<<(E + 255) / 256, 256, 0, s2>>>(ei, E);
    dinv_kernel<<<(M + 255) / 256, 256, 0, s2>>>(M);

    // Main (parallel): weight convert + K1 raw GEMM (Ha = x @ W1)
    setupW_kernel<<<160, 256>>>(W1, W2, W3, lin1_w, lin2_w, lin2_b);
    gemm_kernel<0, 3><<<nt, 256, SMEM>>>(x, nullptr, Ha, Wbase + 0 * F * F,
                                         nullptr, nullptr, 0, M);
    cudaEventRecord(ev[evi], 0);
    cudaStreamWaitEvent(s2, ev[evi], 0);  // s2 now has CSR + K1
    evi++;

    // One layer boundary: agg chunks S->T on s2, gemm chunks T->U on main.
    // U != S, so gemm never clobbers the buffer aggs still gather from.
    auto boundary = [&](const __half* S, __half* T, __half* U,
                        const float* bias, bool raw, const __half* Wt,
                        int gemm_out, const float* gbias2) {
        int firstEv = evi;
        for (int c = 0; c < NCH; c++) {
            int a0 = c * npc;
            int a1 = (a0 + npc < M) ? a0 + npc : M;
            if (a0 >= M) break;
            int wb = (int)(((long long)(a1 - a0) * 16 + 255) / 256);
            if (raw)
                agg_kernel<true><<<wb, 256, 0, s2>>>(S, T, bias, a0, a1);
            else
                agg_kernel<false><<<wb, 256, 0, s2>>>(S, T, bias, a0, a1);
            cudaEventRecord(ev[evi++], s2);
        }
        int e2 = firstEv;
        for (int c = 0; c < NCH; c++) {
            int t0 = c * tpc;
            if (t0 >= nt) break;
            int tc = (t0 + tpc < nt) ? tpc : nt - t0;
            cudaStreamWaitEvent(0, ev[e2++], 0);
            if (gemm_out == 0)
                gemm_kernel<1, 0><<<tc, 256, SMEM>>>(nullptr, T, U, Wt,
                                                     nullptr, nullptr, t0, M);
            else
                gemm_kernel<1, 1><<<tc, 256, SMEM>>>(nullptr, T, U, Wt,
                                                     gbias2, nullptr, t0, M);
        }
        cudaEventRecord(ev[evi], 0);
        cudaStreamWaitEvent(s2, ev[evi], 0);
        evi++;
    };

    // B1: agg Ha->Hb (RAW), gemm Hb->Hc (W2)
    boundary(Ha, Hb, Hc, b1, true, Wbase + 1 * F * F, 0, nullptr);
    // B2: agg Hc->Ha, gemm Ha->Hb (W3)
    boundary(Hc, Ha, Hb, b2, false, Wbase + 2 * F * F, 0, nullptr);
    // B3: agg Hb->Hc, gemm Hc->Ha (lin1, relu)
    boundary(Hb, Hc, Ha, b3, false, Wbase + 3 * F * F, 1, lin1_b);
    // lin2 + log_softmax (reads Ha)
    gemm_kernel<1, 2><<<nt, 256, SMEM>>>(nullptr, Ha, nullptr, Wbase + 4 * F * F,
                                         b2p, out, 0, M);
}

// round 16
// speedup vs baseline: 1.2564x; 1.2564x over previous
#include <cuda_runtime.h>
#include <cuda_fp16.h>
#include <cstdint>
#include <cstddef>

// ---------------------------------------------------------------------------
// GCN: 3x GCNConv(128->128) + lin(128->128,relu) + lin(128->40) + log_softmax
// R13 architecture (best measured 289.1us) + single-pass bucket CSR:
// BM=128 fp16 MMA GEMMs, 16-lane/node uint4 gather agg (8-edge unroll),
// bucket CSR built on a second stream overlapped with weight-convert + K1.
// ---------------------------------------------------------------------------

#define NMAX 100000
#define F    128
#define NCLS 40
#define CAP  128          // bucket capacity; deg ~ Poisson(16), P(>128) ~ 0
#define BM   128

__device__ __half g_Ha[(size_t)NMAX * F];   // ping
__device__ __half g_Hb[(size_t)NMAX * F];   // pong
__device__ float  g_dinv[NMAX];
__device__ int    g_cnt[NMAX];
__device__ int    g_bkt[(size_t)NMAX * CAP];  // bucket adjacency
__device__ __half g_Wh[5 * F * F];            // weights [n][k] fp16
__device__ float  g_b2p[F];
__device__ int    g_is64;

__device__ __forceinline__ float4 h4tof4(uint2 u) {
    __half2 a = *(__half2*)&u.x, b = *(__half2*)&u.y;
    float2 fa = __half22float2(a), fb = __half22float2(b);
    return make_float4(fa.x, fa.y, fb.x, fb.y);
}

// ---------------------------------------------------------------------------
__global__ void setupA_kernel(const unsigned int* __restrict__ w, int M) {
    if (blockIdx.x == 0) {
        __shared__ int found;
        if (threadIdx.x == 0) found = 0;
        __syncthreads();
        for (int i = threadIdx.x; i < 2048; i += blockDim.x)
            if (w[2 * i + 1] != 0u) atomicOr(&found, 1);
        __syncthreads();
        if (threadIdx.x == 0) g_is64 = found ? 0 : 1;
    }
    int stride = gridDim.x * blockDim.x;
    for (int i = blockIdx.x * blockDim.x + threadIdx.x; i < M; i += stride)
        g_cnt[i] = 0;
}

__global__ void setupW_kernel(const float* __restrict__ W1,
                              const float* __restrict__ W2,
                              const float* __restrict__ W3,
                              const float* __restrict__ L1,
                              const float* __restrict__ L2,
                              const float* __restrict__ b2) {
    int stride = gridDim.x * blockDim.x;
    int tid0 = blockIdx.x * blockDim.x + threadIdx.x;
    for (int idx = tid0; idx < 5 * F * F; idx += stride) {
        int wi = idx >> 14;
        int r = idx & 16383;
        int n = r >> 7, k = r & 127;
        float v;
        switch (wi) {
            case 0: v = W1[k * F + n]; break;
            case 1: v = W2[k * F + n]; break;
            case 2: v = W3[k * F + n]; break;
            case 3: v = L1[k * F + n]; break;
            default: v = (n < NCLS) ? L2[k * NCLS + n] : 0.0f; break;
        }
        g_Wh[idx] = __float2half_rn(v);
    }
    for (int i = tid0; i < F; i += stride)
        g_b2p[i] = (i < NCLS) ? b2[i] : 0.0f;
}

__device__ __forceinline__ void load_edge(const void* ei, long long e, long long E,
                                          int& s, int& d) {
    if (g_is64) {
        const long long* p = (const long long*)ei;
        s = (int)p[e];
        d = (int)p[E + e];
    } else {
        const int* p = (const int*)ei;
        s = p[e];
        d = p[E + e];
    }
}

// Single-pass bucket CSR build (replaces hist + scan + fill).
__global__ void bucket_fill_kernel(const void* __restrict__ ei, int E) {
    int e = blockIdx.x * blockDim.x + threadIdx.x;
    if (e >= E) return;
    int s, d;
    load_edge(ei, e, E, s, d);
    int p = atomicAdd(&g_cnt[d], 1);
    if (p < CAP) g_bkt[(size_t)d * CAP + p] = s;
}

__global__ void dinv_kernel(int M) {
    int i = blockIdx.x * blockDim.x + threadIdx.x;
    if (i < M) g_dinv[i] = rsqrtf((float)g_cnt[i] + 1.0f);
}

// ---------------------------------------------------------------------------
// GEMM tile kernel. 256 threads, 128 rows x full K=128.
// smem: A 32KB @0, B 32KB @32768; chunk c of row r at r*256+((c^(r&7))<<4).
//  IN:  0 = fp32 global (x), 1 = half global
//  OUT: 0 = Hdst = h*dinv[row], 1 = Hdst = relu(h+obias), 2 = lsm -> out,
//       3 = Hdst = h (raw)
// ---------------------------------------------------------------------------
__device__ __forceinline__ void mma_f16(float* d, const uint32_t* a, const uint32_t* b) {
    asm volatile(
        "mma.sync.aligned.m16n8k16.row.col.f32.f16.f16.f32 "
        "{%0,%1,%2,%3}, {%4,%5,%6,%7}, {%8,%9}, {%0,%1,%2,%3};"
        : "+f"(d[0]), "+f"(d[1]), "+f"(d[2]), "+f"(d[3])
        : "r"(a[0]), "r"(a[1]), "r"(a[2]), "r"(a[3]), "r"(b[0]), "r"(b[1]));
}

__device__ __forceinline__ void ldmx4(uint32_t* r, uint32_t addr) {
    asm volatile("ldmatrix.sync.aligned.m8n8.x4.shared.b16 {%0,%1,%2,%3}, [%4];"
                 : "=r"(r[0]), "=r"(r[1]), "=r"(r[2]), "=r"(r[3]) : "r"(addr));
}

__device__ __forceinline__ void cp16(uint32_t dst, const void* src, int sz) {
    asm volatile("cp.async.cg.shared.global [%0], [%1], 16, %2;"
                 :: "r"(dst), "l"(src), "r"(sz));
}

__device__ __forceinline__ uint32_t swz(int r, int c) {
    return (uint32_t)(r * 256 + ((c ^ (r & 7)) << 4));
}

template <int IN, int OUT>
__global__ void __launch_bounds__(256, 2) gemm_kernel(
    const float* __restrict__ Ax, const __half* __restrict__ Hsrc,
    __half* __restrict__ Hdst, const __half* __restrict__ Wt,
    const float* __restrict__ obias, float* __restrict__ out, int M)
{
    extern __shared__ __align__(16) char sm[];
    uint32_t sbase;
    asm("{ .reg .u64 t; cvta.to.shared.u64 t, %1; cvt.u32.u64 %0, t; }"
        : "=r"(sbase) : "l"(sm));
    const uint32_t sA = sbase;
    const uint32_t sB = sbase + 32768;

    const int tid = threadIdx.x;
    const int lane = tid & 31;
    const int wid = tid >> 5;
    const int wm = wid & 1;
    const int wn = wid >> 1;
    const int tg = lane >> 2;
    const int tm = lane & 3;
    const int row0 = blockIdx.x * BM;

    // B prefetch
#pragma unroll
    for (int p = 0; p < 8; p++) {
        int q = p * 256 + tid;
        int r = q >> 4, c = q & 15;
        cp16(sB + swz(r, c), Wt + (size_t)r * F + c * 8, 16);
    }

    // A tile
    if (IN == 1) {
#pragma unroll
        for (int p = 0; p < 8; p++) {
            int q = p * 256 + tid;
            int r = q >> 4, c = q & 15;
            int gr = row0 + r;
            cp16(sA + swz(r, c), Hsrc + (size_t)((gr < M) ? gr : 0) * F + c * 8,
                 (gr < M) ? 16 : 0);
        }
        asm volatile("cp.async.commit_group;" ::: "memory");
    } else {
        asm volatile("cp.async.commit_group;" ::: "memory");
#pragma unroll
        for (int p = 0; p < 8; p++) {
            int q = p * 256 + tid;
            int r = q >> 4, c = q & 15;
            int gr = row0 + r;
            float4 v0, v1;
            if (gr < M) {
                size_t o = (size_t)gr * F + c * 8;
                v0 = *(const float4*)(Ax + o);
                v1 = *(const float4*)(Ax + o + 4);
            } else {
                v0 = v1 = make_float4(0.f, 0.f, 0.f, 0.f);
            }
            __half2 a = __floats2half2_rn(v0.x, v0.y);
            __half2 b = __floats2half2_rn(v0.z, v0.w);
            __half2 cc = __floats2half2_rn(v1.x, v1.y);
            __half2 d = __floats2half2_rn(v1.z, v1.w);
            uint32_t ad = sA + swz(r, c);
            asm volatile("st.shared.v4.b32 [%0], {%1,%2,%3,%4};"
                         :: "r"(ad), "r"(*(uint32_t*)&a), "r"(*(uint32_t*)&b),
                            "r"(*(uint32_t*)&cc), "r"(*(uint32_t*)&d));
        }
    }

    asm volatile("cp.async.wait_group 0;" ::: "memory");
    __syncthreads();

    float acc[4][4][4];
#pragma unroll
    for (int mt = 0; mt < 4; mt++)
#pragma unroll
        for (int nt = 0; nt < 4; nt++)
#pragma unroll
            for (int j = 0; j < 4; j++) acc[mt][nt][j] = 0.0f;

#pragma unroll
    for (int kb = 0; kb < 8; kb++) {
        uint32_t af[4][4], bf[2][4];
#pragma unroll
        for (int mt = 0; mt < 4; mt++) {
            int row = wm * 64 + mt * 16 + (lane & 15);
            int cc = kb * 2 + (lane >> 4);
            ldmx4(af[mt], sA + swz(row, cc));
        }
#pragma unroll
        for (int q = 0; q < 2; q++) {
            int n = wn * 32 + q * 16 + ((lane >> 4) << 3) + (lane & 7);
            int cc = kb * 2 + ((lane >> 3) & 1);
            ldmx4(bf[q], sB + swz(n, cc));
        }
#pragma unroll
        for (int mt = 0; mt < 4; mt++)
#pragma unroll
            for (int nt = 0; nt < 4; nt++)
                mma_f16(acc[mt][nt], af[mt], &bf[nt >> 1][2 * (nt & 1)]);
    }
    __syncthreads();

    // Epilogue
    if (OUT == 2) {
        float* stg = (float*)(sm + 32768);  // [128][44]
#pragma unroll
        for (int mt = 0; mt < 4; mt++) {
            int rl0 = wm * 64 + mt * 16 + tg;
#pragma unroll
            for (int nt = 0; nt < 4; nt++) {
                int c = wn * 32 + nt * 8 + 2 * tm;
                if (c < NCLS) {
                    float b0 = obias[c], b1 = obias[c + 1];
                    stg[rl0 * 44 + c] = acc[mt][nt][0] + b0;
                    stg[rl0 * 44 + c + 1] = acc[mt][nt][1] + b1;
                    stg[(rl0 + 8) * 44 + c] = acc[mt][nt][2] + b0;
                    stg[(rl0 + 8) * 44 + c + 1] = acc[mt][nt][3] + b1;
                }
            }
        }
        __syncthreads();
        if (tid < 128) {
            int gr = row0 + tid;
            if (gr < M) {
                const float* rowp = stg + tid * 44;
                float m = -1e30f;
#pragma unroll
                for (int c = 0; c < NCLS; c++) m = fmaxf(m, rowp[c]);
                float s = 0.f;
#pragma unroll
                for (int c = 0; c < NCLS; c++) s += expf(rowp[c] - m);
                float lse = m + logf(s);
                float* op = out + (size_t)gr * NCLS;
#pragma unroll
                for (int c = 0; c < NCLS; c += 4) {
                    float4 v = make_float4(rowp[c] - lse, rowp[c + 1] - lse,
                                           rowp[c + 2] - lse, rowp[c + 3] - lse);
                    *(float4*)(op + c) = v;
                }
            }
        }
    } else {
#pragma unroll
        for (int mt = 0; mt < 4; mt++) {
            int rl0 = wm * 64 + mt * 16 + tg;
            float dv0 = 1.f, dv1 = 1.f;
            if (OUT == 0) {
                int r0g = row0 + rl0, r1g = r0g + 8;
                dv0 = (r0g < M) ? g_dinv[r0g] : 0.f;
                dv1 = (r1g < M) ? g_dinv[r1g] : 0.f;
            }
#pragma unroll
            for (int nt = 0; nt < 4; nt++) {
                int c = wn * 32 + nt * 8 + 2 * tm;
                __half2 v0, v1;
                if (OUT == 0 || OUT == 3) {
                    v0 = __floats2half2_rn(acc[mt][nt][0] * dv0, acc[mt][nt][1] * dv0);
                    v1 = __floats2half2_rn(acc[mt][nt][2] * dv1, acc[mt][nt][3] * dv1);
                } else {
                    float b0 = obias[c], b1 = obias[c + 1];
                    v0 = __floats2half2_rn(fmaxf(acc[mt][nt][0] + b0, 0.f),
                                           fmaxf(acc[mt][nt][1] + b1, 0.f));
                    v1 = __floats2half2_rn(fmaxf(acc[mt][nt][2] + b0, 0.f),
                                           fmaxf(acc[mt][nt][3] + b1, 0.f));
                }
                uint32_t a0 = sA + swz(rl0, c >> 3) + (c & 7) * 2;
                uint32_t a1 = sA + swz(rl0 + 8, c >> 3) + (c & 7) * 2;
                asm volatile("st.shared.b32 [%0], %1;" :: "r"(a0), "r"(*(uint32_t*)&v0));
                asm volatile("st.shared.b32 [%0], %1;" :: "r"(a1), "r"(*(uint32_t*)&v1));
            }
        }
        __syncthreads();
#pragma unroll
        for (int p = 0; p < 8; p++) {
            int q = p * 256 + tid;
            int r = q >> 4, c = q & 15;
            int gr = row0 + r;
            if (gr < M) {
                uint32_t a = sA + swz(r, c);
                uint4 v;
                asm volatile("ld.shared.v4.b32 {%0,%1,%2,%3}, [%4];"
                             : "=r"(v.x), "=r"(v.y), "=r"(v.z), "=r"(v.w) : "r"(a));
                *(uint4*)(Hdst + (size_t)gr * F + c * 8) = v;
            }
        }
    }
}

// ---------------------------------------------------------------------------
// Bucket aggregation, 16 lanes/node, uint4 loads, 8-edge unroll (MLP=8).
// dst[n] = relu(dinv[n]*(sum + self) + bias).
//  RAW=true: Hsrc unscaled; multiply gathered rows by dinv[src].
// ---------------------------------------------------------------------------
template <bool RAW>
__global__ void agg_kernel(const __half* __restrict__ Hsrc,
                           __half* __restrict__ dst,
                           const float* __restrict__ bias, int M) {
    long long t = (long long)blockIdx.x * blockDim.x + threadIdx.x;
    long long n = t >> 4;
    if (n >= M) return;
    int lane = (int)(t & 15);
    const uint4* H = (const uint4*)Hsrc;
    float dn = g_dinv[n];

    uint4 u = H[n * 16 + lane];
    float4 aclo = h4tof4(make_uint2(u.x, u.y));
    float4 achi = h4tof4(make_uint2(u.z, u.w));
    if (RAW) {
        aclo.x *= dn; aclo.y *= dn; aclo.z *= dn; aclo.w *= dn;
        achi.x *= dn; achi.y *= dn; achi.z *= dn; achi.w *= dn;
    }

    int deg = g_cnt[n];
    if (deg > CAP) deg = CAP;
    const int* nb = g_bkt + (size_t)n * CAP;
    int e = 0;

    for (; e + 7 < deg; e += 8) {
        int s[8];
#pragma unroll
        for (int j = 0; j < 8; j++) s[j] = __ldg(&nb[e + j]);
        float d[8];
#pragma unroll
        for (int j = 0; j < 8; j++) d[j] = RAW ? __ldg(&g_dinv[s[j]]) : 1.f;
        uint4 uu[8];
#pragma unroll
        for (int j = 0; j < 8; j++) uu[j] = H[(size_t)s[j] * 16 + lane];
#pragma unroll
        for (int j = 0; j < 8; j++) {
            float4 a = h4tof4(make_uint2(uu[j].x, uu[j].y));
            float4 b = h4tof4(make_uint2(uu[j].z, uu[j].w));
            if (RAW) {
                aclo.x = fmaf(a.x, d[j], aclo.x);
                aclo.y = fmaf(a.y, d[j], aclo.y);
                aclo.z = fmaf(a.z, d[j], aclo.z);
                aclo.w = fmaf(a.w, d[j], aclo.w);
                achi.x = fmaf(b.x, d[j], achi.x);
                achi.y = fmaf(b.y, d[j], achi.y);
                achi.z = fmaf(b.z, d[j], achi.z);
                achi.w = fmaf(b.w, d[j], achi.w);
            } else {
                aclo.x += a.x; aclo.y += a.y; aclo.z += a.z; aclo.w += a.w;
                achi.x += b.x; achi.y += b.y; achi.z += b.z; achi.w += b.w;
            }
        }
    }
    for (; e < deg; e++) {
        int s0 = __ldg(&nb[e]);
        float d0 = RAW ? __ldg(&g_dinv[s0]) : 1.f;
        uint4 u0 = H[(size_t)s0 * 16 + lane];
        float4 a0 = h4tof4(make_uint2(u0.x, u0.y)), b0 = h4tof4(make_uint2(u0.z, u0.w));
        aclo.x += a0.x * d0; aclo.y += a0.y * d0;
        aclo.z += a0.z * d0; aclo.w += a0.w * d0;
        achi.x += b0.x * d0; achi.y += b0.y * d0;
        achi.z += b0.z * d0; achi.w += b0.w * d0;
    }
    float4 blo = *(const float4*)(bias + lane * 8);
    float4 bhi = *(const float4*)(bias + lane * 8 + 4);
    __half2 o0 = __floats2half2_rn(fmaxf(fmaf(aclo.x, dn, blo.x), 0.f),
                                   fmaxf(fmaf(aclo.y, dn, blo.y), 0.f));
    __half2 o1 = __floats2half2_rn(fmaxf(fmaf(aclo.z, dn, blo.z), 0.f),
                                   fmaxf(fmaf(aclo.w, dn, blo.w), 0.f));
    __half2 o2 = __floats2half2_rn(fmaxf(fmaf(achi.x, dn, bhi.x), 0.f),
                                   fmaxf(fmaf(achi.y, dn, bhi.y), 0.f));
    __half2 o3 = __floats2half2_rn(fmaxf(fmaf(achi.z, dn, bhi.z), 0.f),
                                   fmaxf(fmaf(achi.w, dn, bhi.w), 0.f));
    uint4 outv;
    outv.x = *(uint32_t*)&o0; outv.y = *(uint32_t*)&o1;
    outv.z = *(uint32_t*)&o2; outv.w = *(uint32_t*)&o3;
    ((uint4*)dst)[n * 16 + lane] = outv;
}

// ---------------------------------------------------------------------------
extern "C" void kernel_launch(void* const* d_in, const int* in_sizes, int n_in,
                              void* d_out, int out_size) {
    const float* x      = (const float*)d_in[0];
    const void*  ei     = d_in[1];
    const float* W1     = (const float*)d_in[2];
    const float* b1     = (const float*)d_in[3];
    const float* W2     = (const float*)d_in[4];
    const float* b2     = (const float*)d_in[5];
    const float* W3     = (const float*)d_in[6];
    const float* b3     = (const float*)d_in[7];
    const float* lin1_w = (const float*)d_in[8];
    const float* lin1_b = (const float*)d_in[9];
    const float* lin2_w = (const float*)d_in[10];
    const float* lin2_b = (const float*)d_in[11];
    float* out = (float*)d_out;

    int M = in_sizes[0] / F;
    int E = in_sizes[1] / 2;
    const int SMEM = 65536;

    static cudaStream_t s2 = nullptr;
    static cudaEvent_t evFork = nullptr, evJoin = nullptr;
    static bool init_done = false;
    if (!init_done) {
        cudaFuncSetAttribute(gemm_kernel<0, 3>, cudaFuncAttributeMaxDynamicSharedMemorySize, SMEM);
        cudaFuncSetAttribute(gemm_kernel<1, 0>, cudaFuncAttributeMaxDynamicSharedMemorySize, SMEM);
        cudaFuncSetAttribute(gemm_kernel<1, 1>, cudaFuncAttributeMaxDynamicSharedMemorySize, SMEM);
        cudaFuncSetAttribute(gemm_kernel<1, 2>, cudaFuncAttributeMaxDynamicSharedMemorySize, SMEM);
        cudaStreamCreateWithFlags(&s2, cudaStreamNonBlocking);
        cudaEventCreateWithFlags(&evFork, cudaEventDisableTiming);
        cudaEventCreateWithFlags(&evJoin, cudaEventDisableTiming);
        init_done = true;
    }

    __half *Ha, *Hb, *Wbase;
    float* b2p;
    cudaGetSymbolAddress((void**)&Wbase, g_Wh);
    cudaGetSymbolAddress((void**)&Ha, g_Ha);
    cudaGetSymbolAddress((void**)&Hb, g_Hb);
    cudaGetSymbolAddress((void**)&b2p, g_b2p);

    int gb = (M + BM - 1) / BM;
    int wb16 = (int)(((long long)M * 16 + 255) / 256);

    // Front: fork bucket CSR build to s2 after setupA.
    setupA_kernel<<<160, 256>>>((const unsigned int*)ei, M);
    cudaEventRecord(evFork, 0);
    cudaStreamWaitEvent(s2, evFork, 0);
    bucket_fill_kernel<<<(E + 255) / 256, 256, 0, s2>>>(ei, E);
    dinv_kernel<<<(M + 255) / 256, 256, 0, s2>>>(M);
    cudaEventRecord(evJoin, s2);

    // Main stream (parallel): weight convert + K1 raw GEMM (Ha = x @ W1)
    setupW_kernel<<<160, 256>>>(W1, W2, W3, lin1_w, lin2_w, lin2_b);
    gemm_kernel<0, 3><<<gb, 256, SMEM>>>(x, nullptr, Ha, Wbase + 0 * F * F,
                                         nullptr, nullptr, M);

    cudaStreamWaitEvent(0, evJoin, 0);

    // layer 1 agg (RAW: applies dinv[src] during gather)
    agg_kernel<true><<<wb16, 256>>>(Ha, Hb, b1, M);
    // layer 2
    gemm_kernel<1, 0><<<gb, 256, SMEM>>>(nullptr, Hb, Ha, Wbase + 1 * F * F,
                                         nullptr, nullptr, M);
    agg_kernel<false><<<wb16, 256>>>(Ha, Hb, b2, M);
    // layer 3
    gemm_kernel<1, 0><<<gb, 256, SMEM>>>(nullptr, Hb, Ha, Wbase + 2 * F * F,
                                         nullptr, nullptr, M);
    agg_kernel<false><<<wb16, 256>>>(Ha, Hb, b3, M);
    // lin1
    gemm_kernel<1, 1><<<gb, 256, SMEM>>>(nullptr, Hb, Ha, Wbase + 3 * F * F,
                                         lin1_b, nullptr, M);
    // lin2 + log_softmax
    gemm_kernel<1, 2><<<gb, 256, SMEM>>>(nullptr, Ha, nullptr, Wbase + 4 * F * F,
                                         b2p, out, M);
}